// round 15
// baseline (speedup 1.0000x reference)
#include <cuda_runtime.h>

#define NB 8
#define NQ 128
#define NK 512
#define ND 512         // d_q == d_kv
#define DA 256         // d_attn
#define NM (NB * NK)   // 4096 total k rows

#define SCALE2LOG2E 2.8853900817779268f   // 2*log2(e)
#define LOG2E       1.4426950408889634f

// ---------------- scratch (static device globals; no cudaMalloc) ---------------
__device__ float g_qp[NB * NQ * DA];        // (q_proj + bias) * 2log2e
__device__ float g_kpt[DA * NM];            // k_proj transposed+scaled [a][m]
__device__ float g_sc[NB * NQ * NK];        // raw logits (-2 * sum v*sigmoid)
__device__ float g_kvmean[NB * ND];         // per-batch mean kv row

__device__ __forceinline__ float ex2(float x) {
    float r; asm("ex2.approx.f32 %0, %1;" : "=f"(r) : "f"(x)); return r;
}
__device__ __forceinline__ float rcp(float x) {
    float r; asm("rcp.approx.f32 %0, %1;" : "=f"(r) : "f"(x)); return r;
}

// ---------------- K0: per-batch kv mean row. grid (NB, 4) ----------------------
__global__ __launch_bounds__(256) void kvmean_kernel(const float* __restrict__ kv)
{
    const int b = blockIdx.x, dc = blockIdx.y;
    const int tid = threadIdx.x;
    const int dl = tid & 31;        // float4 lane within 128-float chunk
    const int kh = tid >> 5;        // 0..7 k-split
    __shared__ float4 parts[7][32];

    const float4* p = (const float4*)(kv + (size_t)b * NK * ND) + dc * 32 + dl;
    float4 acc = make_float4(0.f, 0.f, 0.f, 0.f);
#pragma unroll 4
    for (int k = kh; k < NK; k += 8) {
        const float4 x = p[(size_t)k * (ND / 4)];
        acc.x += x.x; acc.y += x.y; acc.z += x.z; acc.w += x.w;
    }
    if (kh > 0) parts[kh - 1][dl] = acc;
    __syncthreads();
    if (kh == 0) {
#pragma unroll
        for (int i = 0; i < 7; i++) {
            const float4 t = parts[i][dl];
            acc.x += t.x; acc.y += t.y; acc.z += t.z; acc.w += t.w;
        }
        const float s = 1.0f / (float)NK;
        acc.x *= s; acc.y *= s; acc.z *= s; acc.w *= s;
        ((float4*)(g_kvmean + b * ND))[dc * 32 + dl] = acc;
    }
}

// ---------------- projection GEMM (reads W directly; double-buffered) ----------
// mode 0: g_qp[m][a]  = (X@W[:, :512]^T + bias) * SCALE    (m = b*NQ + q)
// mode 1: g_kpt[a][m] = (X@W[:, 512:]^T) * SCALE           (m = b*NK + k)
__global__ __launch_bounds__(256) void proj_gemm(
    const float* __restrict__ X, const float* __restrict__ W,
    const float* __restrict__ bias, int doff, int rows_per_b,
    const int* __restrict__ lens, int mode)
{
    const int a0 = blockIdx.x * 64;
    const int m0 = blockIdx.y * 64;
    const int b  = m0 / rows_per_b;
    if ((m0 % rows_per_b) >= lens[b]) return;   // whole tile masked

    __shared__ float As[2][16][68];
    __shared__ float Bs[2][16][68];
    const int tid = threadIdx.x;
    const int tx = tid & 15, ty = tid >> 4;

    const int ar = tid >> 2;          // A: m-row 0..63
    const int ac = (tid & 3) * 4;     // A: d-col group
    const int br = tid >> 2;          // B: a-row 0..63
    const int bc = (tid & 3) * 4;     // B: d-col group

    float4 a_reg = *(const float4*)(X + (size_t)(m0 + ar) * ND + ac);
    float4 b_reg = *(const float4*)(W + (size_t)(a0 + br) * 1024 + doff + bc);

    float acc[4][4] = {};
    int buf = 0;

    for (int d0 = 0; d0 < ND; d0 += 16) {
        As[buf][ac + 0][ar] = a_reg.x; As[buf][ac + 1][ar] = a_reg.y;
        As[buf][ac + 2][ar] = a_reg.z; As[buf][ac + 3][ar] = a_reg.w;
        Bs[buf][bc + 0][br] = b_reg.x; Bs[buf][bc + 1][br] = b_reg.y;
        Bs[buf][bc + 2][br] = b_reg.z; Bs[buf][bc + 3][br] = b_reg.w;
        __syncthreads();

        if (d0 + 16 < ND) {
            a_reg = *(const float4*)(X + (size_t)(m0 + ar) * ND + d0 + 16 + ac);
            b_reg = *(const float4*)(W + (size_t)(a0 + br) * 1024 + doff + d0 + 16 + bc);
        }

#pragma unroll
        for (int kk = 0; kk < 16; kk++) {
            float4 afv = *(const float4*)&As[buf][kk][ty * 4];
            float4 bfv = *(const float4*)&Bs[buf][kk][tx * 4];
            float aa[4] = {afv.x, afv.y, afv.z, afv.w};
            float bb[4] = {bfv.x, bfv.y, bfv.z, bfv.w};
#pragma unroll
            for (int i = 0; i < 4; i++)
#pragma unroll
                for (int j = 0; j < 4; j++)
                    acc[i][j] += aa[i] * bb[j];
        }
        buf ^= 1;
    }

    if (mode == 0) {
        float badd[4];
        badd[0] = bias[a0 + tx * 4 + 0];
        badd[1] = bias[a0 + tx * 4 + 1];
        badd[2] = bias[a0 + tx * 4 + 2];
        badd[3] = bias[a0 + tx * 4 + 3];
#pragma unroll
        for (int i = 0; i < 4; i++) {
            const int m = m0 + ty * 4 + i;
            float4 o;
            o.x = (acc[i][0] + badd[0]) * SCALE2LOG2E;
            o.y = (acc[i][1] + badd[1]) * SCALE2LOG2E;
            o.z = (acc[i][2] + badd[2]) * SCALE2LOG2E;
            o.w = (acc[i][3] + badd[3]) * SCALE2LOG2E;
            *(float4*)(g_qp + (size_t)m * DA + a0 + tx * 4) = o;
        }
    } else {
#pragma unroll
        for (int j = 0; j < 4; j++) {
            const int a = a0 + tx * 4 + j;
            float4 o;
            o.x = acc[0][j] * SCALE2LOG2E;
            o.y = acc[1][j] * SCALE2LOG2E;
            o.z = acc[2][j] * SCALE2LOG2E;
            o.w = acc[3][j] * SCALE2LOG2E;
            *(float4*)(g_kpt + (size_t)a * NM + m0 + ty * 4) = o;
        }
    }
}

// ---------------- K1: logits. grid (NB, NQ/4, NK/64); thread = one (k, qi) -----
__global__ __launch_bounds__(256) void score_kernel(
    const float* __restrict__ vvec,
    const int* __restrict__ qlen_p, const int* __restrict__ klen_p)
{
    const int b  = blockIdx.x;
    const int q0 = blockIdx.y * 4;
    const int k0 = blockIdx.z * 64;
    if (q0 >= qlen_p[b] || k0 >= klen_p[b]) return;

    const int tid = threadIdx.x;
    const int kk = tid & 63;
    const int qi = tid >> 6;

    __shared__ float4 qsm[4][DA / 4];
    __shared__ float4 vsm[DA / 4];
    for (int i = tid; i < 4 * (DA / 4); i += 256)
        qsm[i >> 6][i & 63] =
            *(const float4*)(g_qp + (size_t)(b * NQ + q0 + (i >> 6)) * DA + (i & 63) * 4);
    for (int i = tid; i < DA / 4; i += 256)
        vsm[i] = *(const float4*)(vvec + i * 4);
    __syncthreads();

    const float* kpcol = g_kpt + (size_t)b * NK + k0 + kk;   // stride NM per a
    const float4* qrow = qsm[qi];

    float s = 0.f;
    float cur[8], nxt[8];
#pragma unroll
    for (int u = 0; u < 8; u++) cur[u] = kpcol[(size_t)u * NM];

#pragma unroll 2
    for (int a = 0; a < DA - 8; a += 8) {
#pragma unroll
        for (int u = 0; u < 8; u++)
            nxt[u] = kpcol[(size_t)(a + 8 + u) * NM];
#pragma unroll
        for (int g = 0; g < 2; g++) {
            const float4 qv = qrow[(a >> 2) + g];
            const float4 vv = vsm[(a >> 2) + g];
            float r0 = rcp(1.0f + ex2(qv.x + cur[g * 4 + 0]));
            float r1 = rcp(1.0f + ex2(qv.y + cur[g * 4 + 1]));
            float r2 = rcp(1.0f + ex2(qv.z + cur[g * 4 + 2]));
            float r3 = rcp(1.0f + ex2(qv.w + cur[g * 4 + 3]));
            s = fmaf(vv.x, r0, s);
            s = fmaf(vv.y, r1, s);
            s = fmaf(vv.z, r2, s);
            s = fmaf(vv.w, r3, s);
        }
#pragma unroll
        for (int u = 0; u < 8; u++) cur[u] = nxt[u];
    }
#pragma unroll
    for (int g = 0; g < 2; g++) {
        const float4 qv = qrow[((DA - 8) >> 2) + g];
        const float4 vv = vsm[((DA - 8) >> 2) + g];
        float r0 = rcp(1.0f + ex2(qv.x + cur[g * 4 + 0]));
        float r1 = rcp(1.0f + ex2(qv.y + cur[g * 4 + 1]));
        float r2 = rcp(1.0f + ex2(qv.z + cur[g * 4 + 2]));
        float r3 = rcp(1.0f + ex2(qv.w + cur[g * 4 + 3]));
        s = fmaf(vv.x, r0, s);
        s = fmaf(vv.y, r1, s);
        s = fmaf(vv.z, r2, s);
        s = fmaf(vv.w, r3, s);
    }

    g_sc[(size_t)(b * NQ + q0 + qi) * NK + k0 + kk] = -2.0f * s;
}

// ---------------- K2: fused softmax + AV. grid (NB, NQ/4, ND/128) --------------
// Masked rows (q >= qlen) output the precomputed kv mean; probs = 0 for them.
// Active rows: softmax into smem, then AV over k < klen only.
__global__ __launch_bounds__(256) void av_kernel(
    const float* __restrict__ kv,
    const int* __restrict__ qlen_p, const int* __restrict__ klen_p,
    float* __restrict__ out)
{
    const int b  = blockIdx.x;
    const int q0 = blockIdx.y * 4;
    const int dc = blockIdx.z;
    const int tid = threadIdx.x;
    const int qlen = qlen_p[b];
    const int klen = klen_p[b];

    // --- fully masked tile: copy mean row to 4 outputs ---------------------------
    if (q0 >= qlen) {
        if (tid < 32) {
            const float4 u = ((const float4*)(g_kvmean + b * ND))[dc * 32 + tid];
#pragma unroll
            for (int qi = 0; qi < 4; qi++)
                ((float4*)(out + (size_t)(b * NQ + q0 + qi) * ND))[dc * 32 + tid] = u;
        }
        return;
    }

    __shared__ float  psm[NK * 4];       // [k][qi] probs, 8 KB
    __shared__ float  redm[4][2], reds[4][2];
    __shared__ float  izs[4];
    __shared__ float4 parts[7][4][32];   // kh 1..7 partials, 14 KB

    const int w = tid >> 5, lane = tid & 31;
    const int nact = min(qlen - q0, 4);

    // ---- phase 1: softmax (warp = (row qi = w>>1, half h = w&1)) ---------------
    {
        const int qi = w >> 1, h = w & 1;
        const bool masked = (qi >= nact);
        const float* row = g_sc + (size_t)(b * NQ + q0 + qi) * NK + h * 256;

        float vals[8];
        float lmax = -1e30f;
        if (!masked) {
#pragma unroll
            for (int i = 0; i < 8; i++) {
                vals[i] = row[i * 32 + lane];
                const int k = h * 256 + i * 32 + lane;
                if (k < klen) lmax = fmaxf(lmax, vals[i]);
            }
        }
#pragma unroll
        for (int o = 16; o; o >>= 1)
            lmax = fmaxf(lmax, __shfl_xor_sync(0xffffffffu, lmax, o));
        if (lane == 0) redm[qi][h] = lmax;
        __syncthreads();

        const float m = fmaxf(redm[qi][0], redm[qi][1]);
        float lsum = 0.f;
#pragma unroll
        for (int i = 0; i < 8; i++) {
            const int k = h * 256 + i * 32 + lane;
            float e = 0.0f;
            if (!masked && k < klen) e = ex2((vals[i] - m) * LOG2E);
            psm[k * 4 + qi] = e;
            lsum += e;
        }
#pragma unroll
        for (int o = 16; o; o >>= 1)
            lsum += __shfl_xor_sync(0xffffffffu, lsum, o);
        if (lane == 0) reds[qi][h] = lsum;
        __syncthreads();
        if (tid < 4)
            izs[tid] = __fdividef(1.0f, fmaxf(reds[tid][0] + reds[tid][1], 1e-30f));
        __syncthreads();
    }

    // ---- phase 2: AV. thread = (dl: float4 of d, kh: k stride-8 split) ---------
    const int dl = tid & 31, kh = tid >> 5;
    const int klen8 = (klen + 7) & ~7;   // psm is 0 beyond klen, safe
    const float4* kvp = (const float4*)(kv + (size_t)b * NK * ND) + dc * 32 + dl;

    float4 A0 = {0,0,0,0}, A1 = {0,0,0,0}, A2 = {0,0,0,0}, A3 = {0,0,0,0};
    int k = kh;
    if (k < klen8) {
        float4 x = kvp[(size_t)k * (ND / 4)];
        for (; k < klen8; k += 8) {
            float4 xn;
            if (k + 8 < klen8) xn = kvp[(size_t)(k + 8) * (ND / 4)];
            const float4 p = *(const float4*)&psm[k * 4];
            A0.x = fmaf(p.x, x.x, A0.x); A0.y = fmaf(p.x, x.y, A0.y);
            A0.z = fmaf(p.x, x.z, A0.z); A0.w = fmaf(p.x, x.w, A0.w);
            A1.x = fmaf(p.y, x.x, A1.x); A1.y = fmaf(p.y, x.y, A1.y);
            A1.z = fmaf(p.y, x.z, A1.z); A1.w = fmaf(p.y, x.w, A1.w);
            A2.x = fmaf(p.z, x.x, A2.x); A2.y = fmaf(p.z, x.y, A2.y);
            A2.z = fmaf(p.z, x.z, A2.z); A2.w = fmaf(p.z, x.w, A2.w);
            A3.x = fmaf(p.w, x.x, A3.x); A3.y = fmaf(p.w, x.y, A3.y);
            A3.z = fmaf(p.w, x.z, A3.z); A3.w = fmaf(p.w, x.w, A3.w);
            x = xn;
        }
    }

    if (kh > 0) {
        parts[kh - 1][0][dl] = A0; parts[kh - 1][1][dl] = A1;
        parts[kh - 1][2][dl] = A2; parts[kh - 1][3][dl] = A3;
    }
    __syncthreads();
    if (kh == 0) {
        float4 acc[4] = {A0, A1, A2, A3};
#pragma unroll
        for (int qi = 0; qi < 4; qi++) {
#pragma unroll
            for (int p = 0; p < 7; p++) {
                const float4 t = parts[p][qi][dl];
                acc[qi].x += t.x; acc[qi].y += t.y;
                acc[qi].z += t.z; acc[qi].w += t.w;
            }
        }
#pragma unroll
        for (int qi = 0; qi < 4; qi++) {
            float4 o;
            if (qi < nact) {
                const float iz = izs[qi];
                o = make_float4(acc[qi].x * iz, acc[qi].y * iz,
                                acc[qi].z * iz, acc[qi].w * iz);
            } else {
                o = ((const float4*)(g_kvmean + b * ND))[dc * 32 + dl];
            }
            ((float4*)(out + (size_t)(b * NQ + q0 + qi) * ND))[dc * 32 + dl] = o;
        }
    }
}

// ---------------- launch --------------------------------------------------------
extern "C" void kernel_launch(void* const* d_in, const int* in_sizes, int n_in,
                              void* d_out, int out_size)
{
    const float* query = (const float*)d_in[0];
    const float* kv    = (const float*)d_in[1];
    const float* W     = (const float*)d_in[2];
    const float* bias  = (const float*)d_in[3];
    const float* v     = (const float*)d_in[4];
    const int*   qlen  = (const int*)d_in[5];
    const int*   klen  = (const int*)d_in[6];
    float* out = (float*)d_out;

    kvmean_kernel<<<dim3(NB, 4), 256>>>(kv);
    proj_gemm<<<dim3(DA / 64, (NB * NQ) / 64), 256>>>(query, W, bias, 0,   NQ, qlen, 0);
    proj_gemm<<<dim3(DA / 64, (NB * NK) / 64), 256>>>(kv,    W, bias, 512, NK, klen, 1);
    score_kernel<<<dim3(NB, NQ / 4, NK / 64), 256>>>(v, qlen, klen);
    av_kernel<<<dim3(NB, NQ / 4, ND / 128), 256>>>(kv, qlen, klen, out);
}